// round 17
// baseline (speedup 1.0000x reference)
#include <cuda_runtime.h>
#include <cuda_fp16.h>

// Problem constants
#define BB     16384
#define TT     60
#define II     32
#define HH     128
#define STEPS  30
#define SEQOFF 30

#define MT    32       // batch rows per CTA (2 m16 tiles)
#define NTH   256
#define NWARP 8

typedef unsigned int u32;

// ---------------------------------------------------------------------------
// Weight folding: for t>=1, x_t = y_{t-1} = h·Wo^T + bo, so gate pre-acts are
// pure functions of h:  Wcomb = W_ih @ W_out  [384x128],
//   r/z:  single merged matrix (W_hh + Wcomb), 1-pass fp16 (hi only)
//   n  :  aIN via Wcomb_n, aHN via W_hh_n — 1-pass fp16 (hi only)
// Step 0 uses the original K=160 path (real x) with g_B (2-pass, R13 layout).
// ---------------------------------------------------------------------------
__device__ float g_Wcomb[384 * 128];
__device__ float g_bxo[384];

__device__ uint4 g_B[15360];    // t=0 weights: [(w*10+kt)*6+tau]*32+lane (hi,hi,lo,lo)
__device__ uint2 g_Brz[8192];   // t>=1 merged r/z: [(w*8+kt)*4+tau]*32+lane (hi only)
__device__ uint2 g_Bn[8192];    // t>=1 n: tau 0,1=in(Wcomb_n) 2,3=hn(W_hh_n), hi only
__device__ uint4 g_Wo[1024];    // y weights: [(kt*4+nt)*32+lane], hi/lo (2-pass)
__device__ float g_br0[128], g_bz0[128], g_bin0[128];   // t=0 biases
__device__ float g_br1[128], g_bz1[128], g_bin1[128];   // t>=1 (Wx·bo folded)
__device__ float g_bhn[128];

__device__ __forceinline__ u32 f2h2(float a, float b) {
    __half2 h = __floats2half2_rn(a, b);   // a -> low, b -> high
    return *(u32*)&h;
}
__device__ __forceinline__ void packw(float a, float b, u32& hi, u32& lo) {
    __half ha = __float2half_rn(a), hb = __float2half_rn(b);
    hi = ((u32)__half_as_ushort(hb) << 16) | (u32)__half_as_ushort(ha);
    lo = f2h2(a - __half2float(ha), b - __half2float(hb));
}

// pack stage 1: Wcomb = W_ih @ W_out, bxo = W_ih @ b_out
__global__ void pack1(const float* __restrict__ W_ih,
                      const float* __restrict__ W_out,
                      const float* __restrict__ b_out)
{
    int idx = blockIdx.x * blockDim.x + threadIdx.x;
    if (idx < 384 * 128) {
        int col = idx >> 7, j = idx & 127;
        float s = 0.f;
#pragma unroll
        for (int i = 0; i < 32; i++)
            s += W_ih[col * 32 + i] * W_out[i * 128 + j];
        g_Wcomb[idx] = s;
    }
    int i2 = idx - 49152;
    if (i2 >= 0 && i2 < 384) {
        float s = 0.f;
#pragma unroll
        for (int i = 0; i < 32; i++)
            s += W_ih[i2 * 32 + i] * b_out[i];
        g_bxo[i2] = s;
    }
}

// pack stage 2: all fragment-packed weight arrays + biases
__global__ void pack2(const float* __restrict__ W_ih,
                      const float* __restrict__ W_hh,
                      const float* __restrict__ W_out,
                      const float* __restrict__ b_ih,
                      const float* __restrict__ b_hh)
{
    int idx = blockIdx.x * blockDim.x + threadIdx.x;
    if (idx < 15360) {                       // t=0 gate fragments (K=160, 2-pass)
        int lane = idx & 31, tau = (idx >> 5) % 6, kt = (idx / 192) % 10, w = idx / 1920;
        int gate = tau >> 1, nt2 = tau & 1;
        int n = lane >> 2, tg = lane & 3;
        int col = gate * 128 + 16 * w + 8 * nt2 + n;
        float e[4];
#pragma unroll
        for (int q = 0; q < 4; q++) {
            int k = kt * 16 + 2 * tg + (q & 1) + 8 * (q >> 1);
            e[q] = (k < 32) ? W_ih[col * 32 + k] : W_hh[col * 128 + (k - 32)];
        }
        u32 hi0, hi1, lo0, lo1;
        packw(e[0], e[1], hi0, lo0);
        packw(e[2], e[3], hi1, lo1);
        g_B[idx] = make_uint4(hi0, hi1, lo0, lo1);
    }
    int ib = idx - 15360;
    if (ib >= 0 && ib < 8192) {              // merged r/z fragments (hi only)
        int lane = ib & 31, tau = (ib >> 5) & 3, kt = (ib >> 7) & 7, w = ib >> 10;
        int gate = tau >> 1, nt2 = tau & 1;
        int n = lane >> 2, tg = lane & 3;
        int col = gate * 128 + 16 * w + 8 * nt2 + n;
        float e[4];
#pragma unroll
        for (int q = 0; q < 4; q++) {
            int k = kt * 16 + 2 * tg + (q & 1) + 8 * (q >> 1);
            e[q] = W_hh[col * 128 + k] + g_Wcomb[col * 128 + k];
        }
        g_Brz[ib] = make_uint2(f2h2(e[0], e[1]), f2h2(e[2], e[3]));
    }
    int in_ = idx - 23552;
    if (in_ >= 0 && in_ < 8192) {            // n fragments (hi only, 1-pass)
        int lane = in_ & 31, tau = (in_ >> 5) & 3, kt = (in_ >> 7) & 7, w = in_ >> 10;
        int isIn = (tau < 2), nt2 = tau & 1;
        int n = lane >> 2, tg = lane & 3;
        int col = 256 + 16 * w + 8 * nt2 + n;
        float e[4];
#pragma unroll
        for (int q = 0; q < 4; q++) {
            int k = kt * 16 + 2 * tg + (q & 1) + 8 * (q >> 1);
            e[q] = isIn ? g_Wcomb[col * 128 + k] : W_hh[col * 128 + k];
        }
        g_Bn[in_] = make_uint2(f2h2(e[0], e[1]), f2h2(e[2], e[3]));
    }
    int iw = idx - 31744;
    if (iw >= 0 && iw < 1024) {              // W_out fragments (hi/lo, 2-pass)
        int lane = iw & 31, nt = (iw >> 5) & 3, kt = iw >> 7;
        int i = nt * 8 + (lane >> 2), tg = lane & 3;
        float e[4];
#pragma unroll
        for (int q = 0; q < 4; q++) {
            int k = kt * 16 + 2 * tg + (q & 1) + 8 * (q >> 1);
            e[q] = W_out[i * 128 + k];
        }
        u32 hi0, hi1, lo0, lo1;
        packw(e[0], e[1], hi0, lo0);
        packw(e[2], e[3], hi1, lo1);
        g_Wo[iw] = make_uint4(hi0, hi1, lo0, lo1);
    }
    int i4 = idx - 32768;
    if (i4 >= 0 && i4 < 128) {               // biases
        float br = b_ih[i4]       + b_hh[i4];
        float bz = b_ih[128 + i4] + b_hh[128 + i4];
        float bi = b_ih[256 + i4];
        g_br0[i4]  = br;  g_br1[i4]  = br + g_bxo[i4];
        g_bz0[i4]  = bz;  g_bz1[i4]  = bz + g_bxo[128 + i4];
        g_bin0[i4] = bi;  g_bin1[i4] = bi + g_bxo[256 + i4];
        g_bhn[i4]  = b_hh[256 + i4];
    }
}

__device__ __forceinline__ void mma_f16(float (&d)[4], const uint4& a, u32 b0, u32 b1) {
    asm("mma.sync.aligned.m16n8k16.row.col.f32.f16.f16.f32 "
        "{%0,%1,%2,%3},{%4,%5,%6,%7},{%8,%9},{%0,%1,%2,%3};"
        : "+f"(d[0]), "+f"(d[1]), "+f"(d[2]), "+f"(d[3])
        : "r"(a.x), "r"(a.y), "r"(a.z), "r"(a.w), "r"(b0), "r"(b1));
}

// 2-pass (Wh + Wl) MMA into two m-tiles' accumulators
__device__ __forceinline__ void mma_pair(float (&d0)[4], float (&d1)[4],
                                         const uint4& A0, const uint4& A1,
                                         const uint4& wf) {
    mma_f16(d0, A0, wf.x, wf.y);
    mma_f16(d0, A0, wf.z, wf.w);
    mma_f16(d1, A1, wf.x, wf.y);
    mma_f16(d1, A1, wf.z, wf.w);
}

// MUFU.TANH-based activations: 1 MUFU each
__device__ __forceinline__ float tanh_f(float v) {
    float r; asm("tanh.approx.f32 %0, %1;" : "=f"(r) : "f"(v)); return r;
}
__device__ __forceinline__ float sigmoid_f(float v) {
    float t; asm("tanh.approx.f32 %0, %1;" : "=f"(t) : "f"(0.5f * v));
    return fmaf(0.5f, t, 0.5f);
}

// ---------------------------------------------------------------------------
// Recurrent kernel. CTA = 32 batch rows, 8 warps, 30 steps, ONE barrier/step.
// sA: h fragments (fp16), double-buffered, 8 ktiles (K=128). Warp w owns gate
// cols [16w,16w+16) == h ktile w.
// y-GEMM DEFERRED one step: at iter t it computes y_{t-1} from sA[cur] in the
// pre-barrier gap, overlapping the epilogue's MUFU chain (tensor-pipe fill).
// ---------------------------------------------------------------------------
__global__ __launch_bounds__(NTH, 2)
void gru_kernel(const float* __restrict__ x,
                const float* __restrict__ h0,
                const float* __restrict__ b_out,
                float* __restrict__ out)
{
    __shared__ uint4 sA[2][8][2][32];   // 16 KB
    __shared__ uint4 sX[2][2][32];      // 2 KB  (x0 fragments, t=0 only)
    __shared__ uint4 sWo[4][8][32];     // 16 KB (y weights, cached per nty)

    const int tid = threadIdx.x;
    const int w   = tid >> 5;
    const int l   = tid & 31;
    const int b0  = blockIdx.x * MT;
    const int r4  = l >> 2;
    const int c2  = (l & 3) * 2;

    // ---- prologue: h0 fragments (warp w -> ktile w) ----
#pragma unroll
    for (int mt = 0; mt < 2; mt++) {
        float e[8];
#pragma unroll
        for (int q = 0; q < 4; q++) {
            int row = b0 + mt * 16 + r4 + 8 * (q & 1);
            int k   = w * 16 + c2 + 8 * (q >> 1);
            float2 v = *(const float2*)&h0[(size_t)row * HH + k];
            e[2 * q] = v.x; e[2 * q + 1] = v.y;
        }
        sA[0][w][mt][l] = make_uint4(f2h2(e[0], e[1]), f2h2(e[2], e[3]),
                                     f2h2(e[4], e[5]), f2h2(e[6], e[7]));
    }
    // x0 fragments: warps 0-3 -> (kt = w>>1, mt = w&1)
    if (w < 4) {
        const int kt = w >> 1, mt = w & 1;
        float e[8];
#pragma unroll
        for (int q = 0; q < 4; q++) {
            int row = b0 + mt * 16 + r4 + 8 * (q & 1);
            int k   = kt * 16 + c2 + 8 * (q >> 1);
            float2 v = *(const float2*)&x[(size_t)row * (TT * II) + SEQOFF * II + k];
            e[2 * q] = v.x; e[2 * q + 1] = v.y;
        }
        sX[kt][mt][l] = make_uint4(f2h2(e[0], e[1]), f2h2(e[2], e[3]),
                                   f2h2(e[4], e[5]), f2h2(e[6], e[7]));
    }
    // cache y weights: warp w<4 loads nty-slice w
    if (w < 4) {
#pragma unroll
        for (int kt = 0; kt < 8; kt++)
            sWo[w][kt][l] = __ldg(&g_Wo[(kt * 4 + w) * 32 + l]);
    }

    // ---- persistent fp32 hidden state for this warp's 16 cols ----
    float hOld[2][2][4];
#pragma unroll
    for (int mt = 0; mt < 2; mt++)
#pragma unroll
        for (int nt2 = 0; nt2 < 2; nt2++)
#pragma unroll
            for (int rh = 0; rh < 2; rh++) {
                int row = b0 + mt * 16 + r4 + 8 * rh;
                int col = 16 * w + 8 * nt2 + c2;
                float2 v = *(const float2*)&h0[(size_t)row * HH + col];
                hOld[mt][nt2][2 * rh]     = v.x;
                hOld[mt][nt2][2 * rh + 1] = v.y;
            }

    const int mty = w >> 2, nty = w & 3;   // this warp's y-output tile
    const float2 bo2 = *(const float2*)&b_out[nty * 8 + c2];
    __syncthreads();

    for (int t = 0; t < STEPS; t++) {
        const int cur = t & 1, nxt = cur ^ 1;

        float aR[2][2][4], aZ[2][2][4], aIN[2][2][4], aHN[2][2][4];
#pragma unroll
        for (int mt = 0; mt < 2; mt++)
#pragma unroll
            for (int nt2 = 0; nt2 < 2; nt2++)
#pragma unroll
                for (int e = 0; e < 4; e++) {
                    aR[mt][nt2][e] = 0.f; aZ[mt][nt2][e] = 0.f;
                    aIN[mt][nt2][e] = 0.f; aHN[mt][nt2][e] = 0.f;
                }

        if (t == 0) {
            // original K=160 path (real x), 2-pass everywhere
#pragma unroll
            for (int kt = 0; kt < 10; kt++) {
                uint4 A0, A1;
                if (kt < 2) { A0 = sX[kt][0][l];     A1 = sX[kt][1][l]; }
                else        { A0 = sA[0][kt - 2][0][l]; A1 = sA[0][kt - 2][1][l]; }
                const int gb = ((w * 10 + kt) * 6) * 32 + l;
                mma_pair(aR[0][0], aR[1][0], A0, A1, __ldg(&g_B[gb]));
                mma_pair(aR[0][1], aR[1][1], A0, A1, __ldg(&g_B[gb + 32]));
                mma_pair(aZ[0][0], aZ[1][0], A0, A1, __ldg(&g_B[gb + 64]));
                mma_pair(aZ[0][1], aZ[1][1], A0, A1, __ldg(&g_B[gb + 96]));
                if (kt < 2) {
                    mma_pair(aIN[0][0], aIN[1][0], A0, A1, __ldg(&g_B[gb + 128]));
                    mma_pair(aIN[0][1], aIN[1][1], A0, A1, __ldg(&g_B[gb + 160]));
                } else {
                    mma_pair(aHN[0][0], aHN[1][0], A0, A1, __ldg(&g_B[gb + 128]));
                    mma_pair(aHN[0][1], aHN[1][1], A0, A1, __ldg(&g_B[gb + 160]));
                }
            }
        } else {
            // merged K=128 path: ALL gates 1-pass (16 mma/ktile)
#define KT1(KT)                                                                   \
            {                                                                     \
                const uint4 A0 = sA[cur][KT][0][l];                               \
                const uint4 A1 = sA[cur][KT][1][l];                               \
                const int rb = ((w * 8 + (KT)) * 4) * 32 + l;                     \
                const uint2 wr0 = __ldg(&g_Brz[rb]);                              \
                const uint2 wr1 = __ldg(&g_Brz[rb + 32]);                         \
                const uint2 wz0 = __ldg(&g_Brz[rb + 64]);                         \
                const uint2 wz1 = __ldg(&g_Brz[rb + 96]);                         \
                mma_f16(aR[0][0], A0, wr0.x, wr0.y);                              \
                mma_f16(aR[1][0], A1, wr0.x, wr0.y);                              \
                mma_f16(aR[0][1], A0, wr1.x, wr1.y);                              \
                mma_f16(aR[1][1], A1, wr1.x, wr1.y);                              \
                mma_f16(aZ[0][0], A0, wz0.x, wz0.y);                              \
                mma_f16(aZ[1][0], A1, wz0.x, wz0.y);                              \
                mma_f16(aZ[0][1], A0, wz1.x, wz1.y);                              \
                mma_f16(aZ[1][1], A1, wz1.x, wz1.y);                              \
                const uint2 wi0 = __ldg(&g_Bn[rb]);                               \
                const uint2 wi1 = __ldg(&g_Bn[rb + 32]);                          \
                const uint2 wh0 = __ldg(&g_Bn[rb + 64]);                          \
                const uint2 wh1 = __ldg(&g_Bn[rb + 96]);                          \
                mma_f16(aIN[0][0], A0, wi0.x, wi0.y);                             \
                mma_f16(aIN[1][0], A1, wi0.x, wi0.y);                             \
                mma_f16(aIN[0][1], A0, wi1.x, wi1.y);                             \
                mma_f16(aIN[1][1], A1, wi1.x, wi1.y);                             \
                mma_f16(aHN[0][0], A0, wh0.x, wh0.y);                             \
                mma_f16(aHN[1][0], A1, wh0.x, wh0.y);                             \
                mma_f16(aHN[0][1], A0, wh1.x, wh1.y);                             \
                mma_f16(aHN[1][1], A1, wh1.x, wh1.y);                             \
            }
            KT1(0) KT1(1) KT1(2) KT1(3) KT1(4) KT1(5) KT1(6) KT1(7)
#undef KT1
        }

        // ---- epilogue: gates -> h_new (fp32 state), store frag ktile w ----
        const float* brp = (t == 0) ? g_br0 : g_br1;
        const float* bzp = (t == 0) ? g_bz0 : g_bz1;
        const float* bip = (t == 0) ? g_bin0 : g_bin1;
        float hn[2][2][4];
#pragma unroll
        for (int nt2 = 0; nt2 < 2; nt2++) {
            const int cb = 16 * w + 8 * nt2 + c2;
            const float2 brv = *(const float2*)&brp[cb];
            const float2 bzv = *(const float2*)&bzp[cb];
            const float2 biv = *(const float2*)&bip[cb];
            const float2 bhv = *(const float2*)&g_bhn[cb];
#pragma unroll
            for (int mt = 0; mt < 2; mt++)
#pragma unroll
                for (int e = 0; e < 4; e++) {
                    const float bR = (e & 1) ? brv.y : brv.x;
                    const float bZ = (e & 1) ? bzv.y : bzv.x;
                    const float bI = (e & 1) ? biv.y : biv.x;
                    const float bH = (e & 1) ? bhv.y : bhv.x;
                    float r = sigmoid_f(aR[mt][nt2][e] + bR);
                    float z = sigmoid_f(aZ[mt][nt2][e] + bZ);
                    float n = tanh_f(fmaf(r, aHN[mt][nt2][e] + bH,
                                          aIN[mt][nt2][e] + bI));
                    float hv = n + z * (hOld[mt][nt2][e] - n);
                    hOld[mt][nt2][e] = hv;
                    hn[mt][nt2][e] = hv;
                }
        }
#pragma unroll
        for (int mt = 0; mt < 2; mt++) {
            sA[nxt][w][mt][l] = make_uint4(
                f2h2(hn[mt][0][0], hn[mt][0][1]),
                f2h2(hn[mt][0][2], hn[mt][0][3]),
                f2h2(hn[mt][1][0], hn[mt][1][1]),
                f2h2(hn[mt][1][2], hn[mt][1][3]));
        }

        // ---- DEFERRED y-GEMM: y_{t-1} from sA[cur] (h_new of step t-1),
        // issued in the pre-barrier gap so its HMMAs fill the tensor pipe
        // while the epilogue's MUFU chain drains. Bit-identical to the old
        // post-barrier placement (same buffer, same values).
        if (t > 0) {
            float y[4] = {bo2.x, bo2.y, bo2.x, bo2.y};
#pragma unroll
            for (int kt = 0; kt < 8; kt++) {
                const uint4 Ah = sA[cur][kt][mty][l];
                const uint4 wf = sWo[nty][kt][l];
                mma_f16(y, Ah, wf.x, wf.y);
                mma_f16(y, Ah, wf.z, wf.w);
            }
            const size_t row0 = (size_t)b0 + mty * 16 + r4;
            const int col = nty * 8 + c2;
            *(float2*)&out[(row0 * STEPS + (t - 1)) * II + col]       = make_float2(y[0], y[1]);
            *(float2*)&out[((row0 + 8) * STEPS + (t - 1)) * II + col] = make_float2(y[2], y[3]);
        }
        __syncthreads();   // ONLY barrier: h_new fragments visible
    }

    // ---- final y_{STEPS-1} from the last-written buffer ----
    {
        const int fb = STEPS & 1;   // buffer holding h_new of step STEPS-1
        float y[4] = {bo2.x, bo2.y, bo2.x, bo2.y};
#pragma unroll
        for (int kt = 0; kt < 8; kt++) {
            const uint4 Ah = sA[fb][kt][mty][l];
            const uint4 wf = sWo[nty][kt][l];
            mma_f16(y, Ah, wf.x, wf.y);
            mma_f16(y, Ah, wf.z, wf.w);
        }
        const size_t row0 = (size_t)b0 + mty * 16 + r4;
        const int col = nty * 8 + c2;
        *(float2*)&out[(row0 * STEPS + (STEPS - 1)) * II + col]       = make_float2(y[0], y[1]);
        *(float2*)&out[((row0 + 8) * STEPS + (STEPS - 1)) * II + col] = make_float2(y[2], y[3]);
    }
}

// ---------------------------------------------------------------------------
// Harness entry point
// ---------------------------------------------------------------------------
extern "C" void kernel_launch(void* const* d_in, const int* in_sizes, int n_in,
                              void* d_out, int out_size)
{
    const float* x     = (const float*)d_in[0];
    const float* h     = (const float*)d_in[1];
    const float* W_ih  = (const float*)d_in[2];
    const float* W_hh  = (const float*)d_in[3];
    const float* b_ih  = (const float*)d_in[4];
    const float* b_hh  = (const float*)d_in[5];
    const float* W_out = (const float*)d_in[6];
    const float* b_out = (const float*)d_in[7];
    float* out = (float*)d_out;

    pack1<<<194, 256>>>(W_ih, W_out, b_out);
    pack2<<<129, 256>>>(W_ih, W_hh, W_out, b_ih, b_hh);
    gru_kernel<<<BB / MT, NTH>>>(x, h, b_out, out);
}